// round 14
// baseline (speedup 1.0000x reference)
#include <cuda_runtime.h>
#include <cstdint>

#define BATCH 65536
#define NP 2048
#define RPB 16                     /* rows per block */
#define NBLK (BATCH / RPB)         /* 4096 */
#define NT 256
#define NSTEP 8                    /* 2 rows per step */
#define INV_SQRT2F 0.70710678118654752440f

// Per-block partial sums: [blk*8 + comp]
// 0..3 : SumA, SumBr, SumBi, SumC    4..7 : sum(c_r), sum(c_r^2), sum(c_i), sum(c_i^2)
__device__ float g_partials[NBLK * 8];
__device__ int   g_count = 0;

__device__ __forceinline__ void cp_async16(unsigned int smem_addr, const void* gptr) {
    asm volatile("cp.async.cg.shared.global [%0], [%1], 16;\n"
                 :: "r"(smem_addr), "l"(gptr));
}

// Issue one stage: 2 contiguous rows (1024 float4) as 4 x 16B cp.async per thread.
__device__ __forceinline__ void issue_stage(const float4* gbase,
                                            unsigned int stage_base,
                                            int tid, int step, int slot) {
    const float4* gsrc = gbase + (size_t)step * 1024 + tid;
    unsigned int  sdst = stage_base + (unsigned int)slot * 16384u
                       + (unsigned int)tid * 16u;
    cp_async16(sdst,          gsrc);
    cp_async16(sdst + 4096u,  gsrc + 256);
    cp_async16(sdst + 8192u,  gsrc + 512);
    cp_async16(sdst + 12288u, gsrc + 768);
    asm volatile("cp.async.commit_group;\n");
}

#define LANE(e, pw)                                                      \
    {                                                                    \
        float S  = v0.e + v1.e + v2.e + v4.e + v5.e + v6.e;              \
        float ar = fmaf(arc, v3.e, brc);                                 \
        float ai = fmaf(aic, v3.e, bic);                                 \
        float bS = bb * S;                                               \
        sA  = fmaf(pw, fmaf(ar, ar, ai * ai), sA);                       \
        sBr = fmaf(pw, ar * bS, sBr);                                    \
        sBi = fmaf(pw, ai * bS, sBi);                                    \
        sC  = fmaf(pw, bS * bS, sC);                                     \
    }

__global__ __launch_bounds__(NT, 6) void isi_fused_kernel(
    const float* __restrict__ dnn,
    const float* __restrict__ bv,
    const float* __restrict__ hv,
    const float* __restrict__ xr,
    const float* __restrict__ xi,
    const float* __restrict__ isr,   // ISI_symbols_real (B,6)
    const float* __restrict__ isi,   // ISI_symbols_imag (B,6)
    const float* __restrict__ ich,   // ISI_channels     (B,6)
    const float* __restrict__ noise,
    const float* __restrict__ prob,
    float* __restrict__ out)
{
    // Stage ring: 2 slots x 2 rows x 2048 floats = 32 KB.
    // The double scratch for the final combine overlays the ring (reused after
    // the main loop, fenced by __syncthreads).
    __shared__ __align__(16) char smem_raw[2 * 2 * NP * 4];
    float* sstage = (float*)smem_raw;
    __shared__ float scoef[RPB * 5];         // bb, ar_c, ai_c, br_c, bi_c per row
    __shared__ float sred[8 * 8];

    const int tid  = threadIdx.x;
    const int blk  = blockIdx.x;
    const int row0 = blk * RPB;
    const int g    = tid >> 7;               // row-in-step group 0/1
    const int s4   = tid & 127;              // slot within group
    const int t    = (s4 < 74) ? s4 : 73;    // clamped float4 j-slot

    float sA = 0.f, sBr = 0.f, sBi = 0.f, sC = 0.f;
    float sM1r = 0.f, sM2r = 0.f, sM1i = 0.f, sM2i = 0.f;

    // prob float4 covering j = 4t-2 .. 4t+1 (cols 876+4t..879+4t).
    // Zero weights on duplicated/out-of-range lanes.
    float4 p4 = __ldg((const float4*)prob + 219 + t);
    if (s4 >= 74) { p4.x = 0.f; p4.y = 0.f; p4.z = 0.f; p4.w = 0.f; }
    if (t == 0)   { p4.x = 0.f; p4.y = 0.f; }
    if (t == 73)  { p4.z = 0.f; p4.w = 0.f; }

    // Per-row coefficients + moment terms (threads 0..RPB-1)
    if (tid < RPB) {
        const int r = row0 + tid;
        const float bb  = bv[r];
        const float bh  = bb * hv[r];
        const float xrr = xr[r];
        const float xii = xi[r];
        const float nz  = INV_SQRT2F * noise[r];
        scoef[tid * 5 + 0] = bb;
        scoef[tid * 5 + 1] = bh * xrr;
        scoef[tid * 5 + 2] = bh * xii;
        scoef[tid * 5 + 3] = nz - xrr;
        scoef[tid * 5 + 4] = nz - xii;

        const float c  = ich[(size_t)r * 6];
        const float cr = c * isr[(size_t)r * 6];
        const float ci = c * isi[(size_t)r * 6];
        sM1r = cr; sM2r = cr * cr;
        sM1i = ci; sM2i = ci * ci;
    }

    const unsigned int stage_base =
        (unsigned int)__cvta_generic_to_shared(sstage);
    const float4* gbase = (const float4*)(dnn + (size_t)row0 * NP);

    issue_stage(gbase, stage_base, tid, 0, 0);
    issue_stage(gbase, stage_base, tid, 1, 1);
    __syncthreads();   // scoef ready (overlaps with cp.async flight)

    #pragma unroll
    for (int st = 0; st < NSTEP; ++st) {
        if (st < NSTEP - 1) asm volatile("cp.async.wait_group 1;\n");
        else                asm volatile("cp.async.wait_group 0;\n");
        __syncthreads();                       // stage st visible to all

        // compute row 2*st + g from slot st%2
        {
            const float4* rp = (const float4*)(sstage + (st & 1) * 4096
                                               + g * NP) + t;
            float4 v0 = rp[0],   v1 = rp[73],  v2 = rp[146];
            float4 v3 = rp[219], v4 = rp[292], v5 = rp[365];
            float4 v6 = rp[438];
            const int ridx = 2 * st + g;
            const float bb  = scoef[ridx * 5 + 0];
            const float arc = scoef[ridx * 5 + 1];
            const float aic = scoef[ridx * 5 + 2];
            const float brc = scoef[ridx * 5 + 3];
            const float bic = scoef[ridx * 5 + 4];
            LANE(x, p4.x) LANE(y, p4.y) LANE(z, p4.z) LANE(w, p4.w)
        }

        __syncthreads();                       // all reads of slot st%2 done
        if (st + 2 < NSTEP)
            issue_stage(gbase, stage_base, tid, st + 2, st & 1);
    }

    // Block reduction: warp shuffle then across 8 warps via smem
    const unsigned FULL = 0xFFFFFFFFu;
    #pragma unroll
    for (int o = 16; o > 0; o >>= 1) {
        sA   += __shfl_down_sync(FULL, sA, o);
        sBr  += __shfl_down_sync(FULL, sBr, o);
        sBi  += __shfl_down_sync(FULL, sBi, o);
        sC   += __shfl_down_sync(FULL, sC, o);
        sM1r += __shfl_down_sync(FULL, sM1r, o);
        sM2r += __shfl_down_sync(FULL, sM2r, o);
        sM1i += __shfl_down_sync(FULL, sM1i, o);
        sM2i += __shfl_down_sync(FULL, sM2i, o);
    }
    const int warp = tid >> 5, lane = tid & 31;
    if (lane == 0) {
        sred[warp * 8 + 0] = sA;   sred[warp * 8 + 1] = sBr;
        sred[warp * 8 + 2] = sBi;  sred[warp * 8 + 3] = sC;
        sred[warp * 8 + 4] = sM1r; sred[warp * 8 + 5] = sM2r;
        sred[warp * 8 + 6] = sM1i; sred[warp * 8 + 7] = sM2i;
    }
    __syncthreads();
    if (tid < 8) {
        float acc = 0.f;
        #pragma unroll
        for (int w = 0; w < 8; ++w) acc += sred[w * 8 + tid];
        g_partials[blk * 8 + tid] = acc;
    }

    // ---- last-block final combine (deterministic: fixed summation order) ----
    __shared__ int s_last;
    __threadfence();
    __syncthreads();
    if (tid == 0)
        s_last = (atomicAdd(&g_count, 1) == NBLK - 1);
    __syncthreads();
    if (!s_last) return;

    __threadfence();  // acquire: all blocks' partials visible

    double* dsm = (double*)smem_raw;          // overlay: 8*256*8 = 16 KB < 32 KB
    double acc[8];
    #pragma unroll
    for (int c = 0; c < 8; ++c) acc[c] = 0.0;
    for (int b = tid; b < NBLK; b += NT) {
        #pragma unroll
        for (int c = 0; c < 8; ++c)
            acc[c] += (double)g_partials[b * 8 + c];
    }
    #pragma unroll
    for (int c = 0; c < 8; ++c) dsm[c * NT + tid] = acc[c];
    __syncthreads();

    if (tid < 8) {
        double sum = 0.0;
        for (int i = 0; i < NT; ++i) sum += dsm[tid * NT + i];
        dsm[tid] = sum;
    }
    __syncthreads();
    if (tid == 0) {
        const double invB = 1.0 / (double)BATCH;
        double SumA  = dsm[0], SumBr = dsm[1], SumBi = dsm[2], SumC = dsm[3];
        double m1r = dsm[4] * invB, m2r = dsm[5] * invB;
        double m1i = dsm[6] * invB, m2i = dsm[7] * invB;
        out[0] = (float)((SumA + 2.0 * m1r * SumBr + 2.0 * m1i * SumBi
                          + (m2r + m2i) * SumC) * invB);
        g_count = 0;   // self-reset for next graph replay
    }
}

extern "C" void kernel_launch(void* const* d_in, const int* in_sizes, int n_in,
                              void* d_out, int out_size)
{
    const float* dnn   = (const float*)d_in[0];
    const float* bv    = (const float*)d_in[1];
    const float* hv    = (const float*)d_in[2];
    const float* xr    = (const float*)d_in[3];
    const float* xi    = (const float*)d_in[4];
    const float* isr   = (const float*)d_in[5];
    const float* isi   = (const float*)d_in[6];
    const float* ich   = (const float*)d_in[7];
    const float* noise = (const float*)d_in[8];
    const float* prob  = (const float*)d_in[9];

    isi_fused_kernel<<<NBLK, NT>>>(dnn, bv, hv, xr, xi, isr, isi, ich,
                                   noise, prob, (float*)d_out);
}